// round 7
// baseline (speedup 1.0000x reference)
#include <cuda_runtime.h>
#include <cuda_bf16.h>
#include <cstdint>

// Problem constants
#define BATCH 8
#define CI    64
#define CO    128
#define HH    128
#define WW    128
#define HW    (HH*WW)          // 16384

// Scratch: y = conv1x1(x), PIXEL-MAJOR layout: y[b][p][c]. 64 MiB fp32.
__device__ float g_y[BATCH * HW * CO];

// ---- packed f32x2 helpers (Blackwell FFMA2) --------------------------------
__device__ __forceinline__ void fma2(unsigned long long& d,
                                     unsigned long long a,
                                     unsigned long long b) {
    asm("fma.rn.f32x2 %0, %1, %2, %0;" : "+l"(d) : "l"(a), "l"(b));
}
__device__ __forceinline__ void upk2(float& a, float& b, unsigned long long v) {
    asm("mov.b64 {%0, %1}, %2;" : "=f"(a), "=f"(b) : "l"(v));
}
__device__ __forceinline__ unsigned long long dup2(float a) {
    unsigned long long r;
    asm("mov.b64 %0, {%1, %1};" : "=l"(r) : "f"(a));
    return r;
}

// ---------------------------------------------------------------------------
// Kernel 1: 1x1 conv as GEMM with packed fp32x2 FMA, zero in-loop packing.
// Per CTA: 128 output channels x 128 pixels. blockDim=256.
// tx (0..15) = channel group, ty (0..15) = pixel group (8 px each).
// Smem: Wp[i][c] = duplicated (w,w) u64 pairs (64KB); Xs[i][p] floats (32KB).
// Inner loop: LDS.128 of duplicated weights + LDS.128 of x pixel-pairs
// (adjacent floats ARE the packed f32x2 operand) -> 32 FMA2, no movs.
// ---------------------------------------------------------------------------
#define DYN_SMEM (64 * 128 * 8 + 64 * 128 * 4)   // 98304

__global__ void __launch_bounds__(256) conv1x1_kernel(const float* __restrict__ x,
                                                      const float* __restrict__ Wc,
                                                      const float* __restrict__ bc)
{
    extern __shared__ char smraw[];
    unsigned long long* Wp = reinterpret_cast<unsigned long long*>(smraw); // [64][128]
    float* Xs = reinterpret_cast<float*>(smraw + 64 * 128 * 8);            // [64][128]

    const int b   = blockIdx.y;
    const int p0  = blockIdx.x * 128;
    const int tid = threadIdx.x;

    // Fill Wp: Wp[i*128 + c] = (Wc[c][i], Wc[c][i])
    for (int idx = tid; idx < 64 * 128; idx += 256) {
        int i = idx >> 7;
        int c = idx & 127;
        Wp[idx] = dup2(Wc[c * CI + i]);
    }
    // Fill Xs: Xs[i*128 + p] = x[b][i][p0+p]   (float4, coalesced)
    {
        const float4* xb4 = reinterpret_cast<const float4*>(x + (size_t)b * CI * HW);
        float4* Xs4 = reinterpret_cast<float4*>(Xs);
        for (int idx = tid; idx < 2048; idx += 256) {
            int i  = idx >> 5;
            int p4 = idx & 31;
            Xs4[idx] = xb4[i * (HW / 4) + (p0 >> 2) + p4];
        }
    }
    __syncthreads();

    const int tx = tid & 15;   // channel group
    const int ty = tid >> 4;   // pixel group

    // acc2[q][k]: pixel-pair q (pixels 2q,2q+1 of this thread's 8),
    // k 0..3 -> channel tx*4+k ; k 4..7 -> channel 64+tx*4+(k-4)
    unsigned long long acc2[4][8];
#pragma unroll
    for (int q = 0; q < 4; ++q)
#pragma unroll
        for (int k = 0; k < 8; ++k) acc2[q][k] = 0ull;

#pragma unroll 4
    for (int i = 0; i < 64; ++i) {
        const unsigned long long* wrow = Wp + i * 128;
        const float* xrow = Xs + i * 128;

        // 4 LDS.128 of duplicated weights (no packing needed)
        ulonglong2 wa = *reinterpret_cast<const ulonglong2*>(wrow + tx * 4);
        ulonglong2 wb = *reinterpret_cast<const ulonglong2*>(wrow + tx * 4 + 2);
        ulonglong2 wc2 = *reinterpret_cast<const ulonglong2*>(wrow + 64 + tx * 4);
        ulonglong2 wd2 = *reinterpret_cast<const ulonglong2*>(wrow + 64 + tx * 4 + 2);
        unsigned long long wd[8] = {wa.x, wa.y, wb.x, wb.y,
                                    wc2.x, wc2.y, wd2.x, wd2.y};

        // 2 LDS.128 of x: adjacent floats = packed f32x2 pairs
        ulonglong2 xa = *reinterpret_cast<const ulonglong2*>(xrow + ty * 8);
        ulonglong2 xb = *reinterpret_cast<const ulonglong2*>(xrow + ty * 8 + 4);
        unsigned long long xp[4] = {xa.x, xa.y, xb.x, xb.y};

#pragma unroll
        for (int q = 0; q < 4; ++q)
#pragma unroll
            for (int k = 0; k < 8; ++k)
                fma2(acc2[q][k], xp[q], wd[k]);
    }

    // Bias
    float bv[8];
#pragma unroll
    for (int k = 0; k < 4; ++k) {
        bv[k]     = bc[tx * 4 + k];
        bv[k + 4] = bc[64 + tx * 4 + k];
    }

    // Write y pixel-major: y[(b*HW + p)*128 + c]
    float* yb = g_y + ((size_t)b * HW + p0) * CO;
#pragma unroll
    for (int q = 0; q < 4; ++q) {
        float e[2][8];
#pragma unroll
        for (int k = 0; k < 8; ++k) {
            float lo, hi;
            upk2(lo, hi, acc2[q][k]);
            e[0][k] = lo + bv[k];
            e[1][k] = hi + bv[k];
        }
#pragma unroll
        for (int half = 0; half < 2; ++half) {
            float* dst = yb + (size_t)(ty * 8 + q * 2 + half) * CO;
            float4 r0 = make_float4(e[half][0], e[half][1], e[half][2], e[half][3]);
            float4 r1 = make_float4(e[half][4], e[half][5], e[half][6], e[half][7]);
            reinterpret_cast<float4*>(dst + tx * 4)[0]      = r0;
            reinterpret_cast<float4*>(dst + 64 + tx * 4)[0] = r1;
        }
    }
}

// ---------------------------------------------------------------------------
// Kernel 2: 3x3 local attention, warp per 1x2 pixel strip, register resident.
// (best-known variant, unchanged)
// ---------------------------------------------------------------------------
__global__ void __launch_bounds__(256) attn3x3_kernel(float* __restrict__ out)
{
    __shared__ float so[16 * CO];  // [pix][c]

    const int tid  = threadIdx.x;
    const int wid  = tid >> 5;
    const int lane = tid & 31;

    const int g16 = blockIdx.x * 16;
    const int b   = g16 >> 14;
    const int p   = g16 & (HW - 1);
    const int h   = p >> 7;
    const int wc  = p & (WW - 1);
    const int w0  = wc + wid * 2;

    const float* ybase = g_y + ((size_t)b * HW) * CO + lane * 4;

    float4 v[3][4];
#pragma unroll
    for (int r = 0; r < 3; ++r) {
        int gh = h - 1 + r;
#pragma unroll
        for (int c = 0; c < 4; ++c) {
            int gw = w0 - 1 + c;
            if ((unsigned)gh < HH && (unsigned)gw < WW) {
                v[r][c] = *reinterpret_cast<const float4*>(
                    ybase + (size_t)(gh * WW + gw) * CO);
            } else {
                v[r][c] = make_float4(0.f, 0.f, 0.f, 0.f);
            }
        }
    }

    const float scale = 0.08838834764831845f; // 1/sqrt(128)

#pragma unroll
    for (int j = 0; j < 2; ++j) {
        const float4 mid = v[1][j + 1];

        float s[9];
#pragma unroll
        for (int n = 0; n < 9; ++n) {
            const float4 q = v[n / 3][j + n % 3];
            s[n] = q.x * mid.x + q.y * mid.y + q.z * mid.z + q.w * mid.w;
        }

#pragma unroll
        for (int off = 16; off > 0; off >>= 1) {
#pragma unroll
            for (int n = 0; n < 9; ++n)
                s[n] += __shfl_xor_sync(0xffffffffu, s[n], off);
        }

        float mx = s[0];
#pragma unroll
        for (int n = 1; n < 9; ++n) mx = fmaxf(mx, s[n]);
        float a[9], den = 0.f;
#pragma unroll
        for (int n = 0; n < 9; ++n) {
            a[n] = __expf((s[n] - mx) * scale);
            den += a[n];
        }
        float inv = 1.0f / den;

        float4 o = make_float4(0.f, 0.f, 0.f, 0.f);
#pragma unroll
        for (int n = 0; n < 9; ++n) {
            const float4 q = v[n / 3][j + n % 3];
            float an = a[n] * inv;
            o.x = fmaf(an, q.x, o.x);
            o.y = fmaf(an, q.y, o.y);
            o.z = fmaf(an, q.z, o.z);
            o.w = fmaf(an, q.w, o.w);
        }

        *reinterpret_cast<float4*>(&so[(wid * 2 + j) * CO + lane * 4]) = o;
    }
    __syncthreads();

    {
        const int c  = tid >> 1;
        const int qb = (tid & 1) * 2;
        float* dst = out + ((size_t)b * CO + c) * HW + h * WW + wc;
#pragma unroll
        for (int j = 0; j < 2; ++j) {
            int q = qb + j;
            float4 r;
            r.x = so[(q * 4 + 0) * CO + c];
            r.y = so[(q * 4 + 1) * CO + c];
            r.z = so[(q * 4 + 2) * CO + c];
            r.w = so[(q * 4 + 3) * CO + c];
            *reinterpret_cast<float4*>(dst + q * 4) = r;
        }
    }
}

// ---------------------------------------------------------------------------
extern "C" void kernel_launch(void* const* d_in, const int* in_sizes, int n_in,
                              void* d_out, int out_size)
{
    const float* x  = nullptr;
    const float* Wc = nullptr;
    const float* bc = nullptr;
    for (int i = 0; i < n_in; ++i) {
        if (in_sizes[i] == BATCH * CI * HW) x  = (const float*)d_in[i];
        else if (in_sizes[i] == CO * CI)    Wc = (const float*)d_in[i];
        else if (in_sizes[i] == CO)         bc = (const float*)d_in[i];
    }
    float* out = (float*)d_out;

    cudaFuncSetAttribute(conv1x1_kernel,
                         cudaFuncAttributeMaxDynamicSharedMemorySize, DYN_SMEM);

    conv1x1_kernel<<<dim3(HW / 128, BATCH), 256, DYN_SMEM>>>(x, Wc, bc);
    attn3x3_kernel<<<BATCH * HW / 16, 256>>>(out);
}

// round 8
// speedup vs baseline: 1.3292x; 1.3292x over previous
#include <cuda_runtime.h>
#include <cuda_fp16.h>
#include <cstdint>

// Problem constants
#define BATCH 8
#define CI    64
#define CO    128
#define HH    128
#define WW    128
#define HW    (HH*WW)          // 16384

// Scratch: y = conv1x1(x), PIXEL-MAJOR, fp16: y[b][p][c]. 32 MiB.
__device__ __half g_y[BATCH * HW * CO];

// ---- packed f32x2 helpers (Blackwell FFMA2) --------------------------------
__device__ __forceinline__ unsigned long long pk2(float a, float b) {
    unsigned long long r;
    asm("mov.b64 %0, {%1, %2};" : "=l"(r) : "f"(a), "f"(b));
    return r;
}
__device__ __forceinline__ void fma2(unsigned long long& d,
                                     unsigned long long a,
                                     unsigned long long b) {
    asm("fma.rn.f32x2 %0, %1, %2, %0;" : "+l"(d) : "l"(a), "l"(b));
}
__device__ __forceinline__ void upk2(float& a, float& b, unsigned long long v) {
    asm("mov.b64 {%0, %1}, %2;" : "=f"(a), "=f"(b) : "l"(v));
}

// half2-pair (4 channels) -> float4
__device__ __forceinline__ float4 h2f4(uint2 u) {
    __half2 a = *reinterpret_cast<__half2*>(&u.x);
    __half2 b = *reinterpret_cast<__half2*>(&u.y);
    float2 fa = __half22float2(a);
    float2 fb = __half22float2(b);
    return make_float4(fa.x, fa.y, fb.x, fb.y);
}

// ---------------------------------------------------------------------------
// Kernel 1: 1x1 conv, FFMA2 GEMM (proven R3 core). Per CTA: 128 ch x 128 px.
// blockDim=256: tx = channel group (8 ch), ty = pixel group (8 px).
// X pairs come straight from LDS.128 (adjacent floats = packed f32x2).
// W packed via 8 dup-movs/iter. Epilogue: fp16 stores to pixel-major y.
// ---------------------------------------------------------------------------
__global__ void __launch_bounds__(256) conv1x1_kernel(const float* __restrict__ x,
                                                      const float* __restrict__ Wc,
                                                      const float* __restrict__ bc)
{
    extern __shared__ float sm[];
    float* Ws = sm;            // [i][o] 64*128 (Wc transposed)
    float* Xs = sm + 64 * 128; // [i][p] 64*128

    const int b   = blockIdx.y;
    const int p0  = blockIdx.x * 128;
    const int tid = threadIdx.x;

    for (int idx = tid; idx < 64 * 128; idx += 256) {
        int i = idx >> 7;
        int o = idx & 127;
        Ws[idx] = Wc[o * CI + i];
    }
    {
        const float4* xb4 = reinterpret_cast<const float4*>(x + (size_t)b * CI * HW);
        float4* Xs4 = reinterpret_cast<float4*>(Xs);
        for (int idx = tid; idx < 2048; idx += 256) {
            int i  = idx >> 5;
            int p4 = idx & 31;
            Xs4[idx] = xb4[i * (HW / 4) + (p0 >> 2) + p4];
        }
    }
    __syncthreads();

    const int tx = tid & 15;   // channel group
    const int ty = tid >> 4;   // pixel group

    unsigned long long acc2[4][8];
#pragma unroll
    for (int q = 0; q < 4; ++q)
#pragma unroll
        for (int k = 0; k < 8; ++k) acc2[q][k] = 0ull;

    const float4* Ws4 = reinterpret_cast<const float4*>(Ws);

#pragma unroll 4
    for (int i = 0; i < 64; ++i) {
        float4 w0 = Ws4[i * 32 + tx];         // channels tx*4..+3
        float4 w1 = Ws4[i * 32 + 16 + tx];    // channels 64+tx*4..+3

        // X: adjacent floats ARE packed f32x2 pairs (no packing)
        const float* xrow = Xs + i * 128;
        ulonglong2 xa = *reinterpret_cast<const ulonglong2*>(xrow + ty * 8);
        ulonglong2 xb = *reinterpret_cast<const ulonglong2*>(xrow + ty * 8 + 4);
        unsigned long long xp[4] = {xa.x, xa.y, xb.x, xb.y};

        unsigned long long wd[8];
        wd[0] = pk2(w0.x, w0.x); wd[1] = pk2(w0.y, w0.y);
        wd[2] = pk2(w0.z, w0.z); wd[3] = pk2(w0.w, w0.w);
        wd[4] = pk2(w1.x, w1.x); wd[5] = pk2(w1.y, w1.y);
        wd[6] = pk2(w1.z, w1.z); wd[7] = pk2(w1.w, w1.w);

#pragma unroll
        for (int q = 0; q < 4; ++q)
#pragma unroll
            for (int k = 0; k < 8; ++k)
                fma2(acc2[q][k], xp[q], wd[k]);
    }

    // Bias
    float bv[8];
#pragma unroll
    for (int k = 0; k < 4; ++k) {
        bv[k]     = bc[tx * 4 + k];
        bv[k + 4] = bc[64 + tx * 4 + k];
    }

    // Write y pixel-major fp16: y[(b*HW + p)*128 + c]
    __half* yb = g_y + ((size_t)b * HW + p0) * CO;
#pragma unroll
    for (int q = 0; q < 4; ++q) {
#pragma unroll
        for (int half = 0; half < 2; ++half) {
            float e[8];
#pragma unroll
            for (int k = 0; k < 8; ++k) {
                float lo, hi;
                upk2(lo, hi, acc2[q][k]);
                e[k] = (half == 0 ? lo : hi) + bv[k];
            }
            __half* dst = yb + (size_t)(ty * 8 + q * 2 + half) * CO;
            __half2 h0 = __floats2half2_rn(e[0], e[1]);
            __half2 h1 = __floats2half2_rn(e[2], e[3]);
            __half2 h2 = __floats2half2_rn(e[4], e[5]);
            __half2 h3 = __floats2half2_rn(e[6], e[7]);
            *reinterpret_cast<uint2*>(dst + tx * 4) =
                make_uint2(*reinterpret_cast<uint32_t*>(&h0),
                           *reinterpret_cast<uint32_t*>(&h1));
            *reinterpret_cast<uint2*>(dst + 64 + tx * 4) =
                make_uint2(*reinterpret_cast<uint32_t*>(&h2),
                           *reinterpret_cast<uint32_t*>(&h3));
        }
    }
}

// ---------------------------------------------------------------------------
// Kernel 2: 3x3 local attention, warp per 1x2 pixel strip.
// y is fp16: each lane loads 4 channels as LDG.64 (uint2 = 2 half2),
// converts ONCE to float4 registers, then proven fp32 compute path.
// ---------------------------------------------------------------------------
__global__ void __launch_bounds__(256) attn3x3_kernel(float* __restrict__ out)
{
    __shared__ float so[16 * CO];  // [pix][c]

    const int tid  = threadIdx.x;
    const int wid  = tid >> 5;
    const int lane = tid & 31;

    const int g16 = blockIdx.x * 16;
    const int b   = g16 >> 14;
    const int p   = g16 & (HW - 1);
    const int h   = p >> 7;
    const int wc  = p & (WW - 1);
    const int w0  = wc + wid * 2;

    const __half* ybase = g_y + ((size_t)b * HW) * CO + lane * 4;

    // Load 3x4 neighborhood as fp16, convert once to fp32 regs
    float4 v[3][4];
#pragma unroll
    for (int r = 0; r < 3; ++r) {
        int gh = h - 1 + r;
#pragma unroll
        for (int c = 0; c < 4; ++c) {
            int gw = w0 - 1 + c;
            if ((unsigned)gh < HH && (unsigned)gw < WW) {
                uint2 u = *reinterpret_cast<const uint2*>(
                    ybase + (size_t)(gh * WW + gw) * CO);
                v[r][c] = h2f4(u);
            } else {
                v[r][c] = make_float4(0.f, 0.f, 0.f, 0.f);
            }
        }
    }

    const float scale = 0.08838834764831845f; // 1/sqrt(128)

#pragma unroll
    for (int j = 0; j < 2; ++j) {
        const float4 mid = v[1][j + 1];

        float s[9];
#pragma unroll
        for (int n = 0; n < 9; ++n) {
            const float4 q = v[n / 3][j + n % 3];
            s[n] = q.x * mid.x + q.y * mid.y + q.z * mid.z + q.w * mid.w;
        }

#pragma unroll
        for (int off = 16; off > 0; off >>= 1) {
#pragma unroll
            for (int n = 0; n < 9; ++n)
                s[n] += __shfl_xor_sync(0xffffffffu, s[n], off);
        }

        float mx = s[0];
#pragma unroll
        for (int n = 1; n < 9; ++n) mx = fmaxf(mx, s[n]);
        float a[9], den = 0.f;
#pragma unroll
        for (int n = 0; n < 9; ++n) {
            a[n] = __expf((s[n] - mx) * scale);
            den += a[n];
        }
        float inv = 1.0f / den;

        float4 o = make_float4(0.f, 0.f, 0.f, 0.f);
#pragma unroll
        for (int n = 0; n < 9; ++n) {
            const float4 q = v[n / 3][j + n % 3];
            float an = a[n] * inv;
            o.x = fmaf(an, q.x, o.x);
            o.y = fmaf(an, q.y, o.y);
            o.z = fmaf(an, q.z, o.z);
            o.w = fmaf(an, q.w, o.w);
        }

        *reinterpret_cast<float4*>(&so[(wid * 2 + j) * CO + lane * 4]) = o;
    }
    __syncthreads();

    {
        const int c  = tid >> 1;
        const int qb = (tid & 1) * 2;
        float* dst = out + ((size_t)b * CO + c) * HW + h * WW + wc;
#pragma unroll
        for (int j = 0; j < 2; ++j) {
            int q = qb + j;
            float4 r;
            r.x = so[(q * 4 + 0) * CO + c];
            r.y = so[(q * 4 + 1) * CO + c];
            r.z = so[(q * 4 + 2) * CO + c];
            r.w = so[(q * 4 + 3) * CO + c];
            *reinterpret_cast<float4*>(dst + q * 4) = r;
        }
    }
}

// ---------------------------------------------------------------------------
extern "C" void kernel_launch(void* const* d_in, const int* in_sizes, int n_in,
                              void* d_out, int out_size)
{
    const float* x  = nullptr;
    const float* Wc = nullptr;
    const float* bc = nullptr;
    for (int i = 0; i < n_in; ++i) {
        if (in_sizes[i] == BATCH * CI * HW) x  = (const float*)d_in[i];
        else if (in_sizes[i] == CO * CI)    Wc = (const float*)d_in[i];
        else if (in_sizes[i] == CO)         bc = (const float*)d_in[i];
    }
    float* out = (float*)d_out;

    static const int conv_smem = 64 * 128 * 2 * sizeof(float);   // 65536

    cudaFuncSetAttribute(conv1x1_kernel,
                         cudaFuncAttributeMaxDynamicSharedMemorySize, conv_smem);

    conv1x1_kernel<<<dim3(HW / 128, BATCH), 256, conv_smem>>>(x, Wc, bc);
    attn3x3_kernel<<<BATCH * HW / 16, 256>>>(out);
}

// round 9
// speedup vs baseline: 1.3786x; 1.0372x over previous
#include <cuda_runtime.h>
#include <cuda_fp16.h>
#include <cstdint>

// Problem constants
#define BATCH 8
#define CI    64
#define CO    128
#define HH    128
#define WW    128
#define HW    (HH*WW)          // 16384

// Scratch: y = conv1x1(x), PIXEL-MAJOR, fp16: y[b][p][c]. 32 MiB.
__device__ __half g_y[BATCH * HW * CO];

// ---- packed f32x2 helpers (Blackwell FFMA2) --------------------------------
__device__ __forceinline__ unsigned long long pk2(float a, float b) {
    unsigned long long r;
    asm("mov.b64 %0, {%1, %2};" : "=l"(r) : "f"(a), "f"(b));
    return r;
}
__device__ __forceinline__ void fma2(unsigned long long& d,
                                     unsigned long long a,
                                     unsigned long long b) {
    asm("fma.rn.f32x2 %0, %1, %2, %0;" : "+l"(d) : "l"(a), "l"(b));
}
__device__ __forceinline__ void upk2(float& a, float& b, unsigned long long v) {
    asm("mov.b64 {%0, %1}, %2;" : "=f"(a), "=f"(b) : "l"(v));
}

// half2-pair (4 channels) -> float4
__device__ __forceinline__ float4 h2f4(uint2 u) {
    __half2 a = *reinterpret_cast<__half2*>(&u.x);
    __half2 b = *reinterpret_cast<__half2*>(&u.y);
    float2 fa = __half22float2(a);
    float2 fb = __half22float2(b);
    return make_float4(fa.x, fa.y, fb.x, fb.y);
}

// ---------------------------------------------------------------------------
// Kernel 1: 1x1 conv, FFMA2 GEMM (proven R8 core, unchanged).
// ---------------------------------------------------------------------------
__global__ void __launch_bounds__(256) conv1x1_kernel(const float* __restrict__ x,
                                                      const float* __restrict__ Wc,
                                                      const float* __restrict__ bc)
{
    extern __shared__ float sm[];
    float* Ws = sm;            // [i][o] 64*128 (Wc transposed)
    float* Xs = sm + 64 * 128; // [i][p] 64*128

    const int b   = blockIdx.y;
    const int p0  = blockIdx.x * 128;
    const int tid = threadIdx.x;

    for (int idx = tid; idx < 64 * 128; idx += 256) {
        int i = idx >> 7;
        int o = idx & 127;
        Ws[idx] = Wc[o * CI + i];
    }
    {
        const float4* xb4 = reinterpret_cast<const float4*>(x + (size_t)b * CI * HW);
        float4* Xs4 = reinterpret_cast<float4*>(Xs);
        for (int idx = tid; idx < 2048; idx += 256) {
            int i  = idx >> 5;
            int p4 = idx & 31;
            Xs4[idx] = xb4[i * (HW / 4) + (p0 >> 2) + p4];
        }
    }
    __syncthreads();

    const int tx = tid & 15;   // channel group
    const int ty = tid >> 4;   // pixel group

    unsigned long long acc2[4][8];
#pragma unroll
    for (int q = 0; q < 4; ++q)
#pragma unroll
        for (int k = 0; k < 8; ++k) acc2[q][k] = 0ull;

    const float4* Ws4 = reinterpret_cast<const float4*>(Ws);

#pragma unroll 4
    for (int i = 0; i < 64; ++i) {
        float4 w0 = Ws4[i * 32 + tx];
        float4 w1 = Ws4[i * 32 + 16 + tx];

        const float* xrow = Xs + i * 128;
        ulonglong2 xa = *reinterpret_cast<const ulonglong2*>(xrow + ty * 8);
        ulonglong2 xb = *reinterpret_cast<const ulonglong2*>(xrow + ty * 8 + 4);
        unsigned long long xp[4] = {xa.x, xa.y, xb.x, xb.y};

        unsigned long long wd[8];
        wd[0] = pk2(w0.x, w0.x); wd[1] = pk2(w0.y, w0.y);
        wd[2] = pk2(w0.z, w0.z); wd[3] = pk2(w0.w, w0.w);
        wd[4] = pk2(w1.x, w1.x); wd[5] = pk2(w1.y, w1.y);
        wd[6] = pk2(w1.z, w1.z); wd[7] = pk2(w1.w, w1.w);

#pragma unroll
        for (int q = 0; q < 4; ++q)
#pragma unroll
            for (int k = 0; k < 8; ++k)
                fma2(acc2[q][k], xp[q], wd[k]);
    }

    float bv[8];
#pragma unroll
    for (int k = 0; k < 4; ++k) {
        bv[k]     = bc[tx * 4 + k];
        bv[k + 4] = bc[64 + tx * 4 + k];
    }

    __half* yb = g_y + ((size_t)b * HW + p0) * CO;
#pragma unroll
    for (int q = 0; q < 4; ++q) {
#pragma unroll
        for (int half = 0; half < 2; ++half) {
            float e[8];
#pragma unroll
            for (int k = 0; k < 8; ++k) {
                float lo, hi;
                upk2(lo, hi, acc2[q][k]);
                e[k] = (half == 0 ? lo : hi) + bv[k];
            }
            __half* dst = yb + (size_t)(ty * 8 + q * 2 + half) * CO;
            __half2 h0 = __floats2half2_rn(e[0], e[1]);
            __half2 h1 = __floats2half2_rn(e[2], e[3]);
            __half2 h2 = __floats2half2_rn(e[4], e[5]);
            __half2 h3 = __floats2half2_rn(e[6], e[7]);
            *reinterpret_cast<uint2*>(dst + tx * 4) =
                make_uint2(*reinterpret_cast<uint32_t*>(&h0),
                           *reinterpret_cast<uint32_t*>(&h1));
            *reinterpret_cast<uint2*>(dst + 64 + tx * 4) =
                make_uint2(*reinterpret_cast<uint32_t*>(&h2),
                           *reinterpret_cast<uint32_t*>(&h3));
        }
    }
}

// ---------------------------------------------------------------------------
// Kernel 2: 3x3 local attention, warp per 1x2 strip, SPLIT-BUTTERFLY reduce.
// After one xor-16 stage, lanes 0-15 carry pixel A's scores and lanes 16-31
// carry pixel B's; 4 more stages reduce both at once. Each lane runs softmax
// for its own pixel only (9 exp), then xor-16 shuffles exchange weights.
// ---------------------------------------------------------------------------
__global__ void __launch_bounds__(256) attn3x3_kernel(float* __restrict__ out)
{
    __shared__ float so[16 * CO];  // [pix][c]

    const int tid  = threadIdx.x;
    const int wid  = tid >> 5;
    const int lane = tid & 31;

    const int g16 = blockIdx.x * 16;
    const int b   = g16 >> 14;
    const int p   = g16 & (HW - 1);
    const int h   = p >> 7;
    const int wc  = p & (WW - 1);
    const int w0  = wc + wid * 2;

    const __half* ybase = g_y + ((size_t)b * HW) * CO + lane * 4;

    // Load 3x4 neighborhood as fp16, convert once to fp32 regs
    float4 v[3][4];
#pragma unroll
    for (int r = 0; r < 3; ++r) {
        int gh = h - 1 + r;
#pragma unroll
        for (int c = 0; c < 4; ++c) {
            int gw = w0 - 1 + c;
            if ((unsigned)gh < HH && (unsigned)gw < WW) {
                uint2 u = *reinterpret_cast<const uint2*>(
                    ybase + (size_t)(gh * WW + gw) * CO);
                v[r][c] = h2f4(u);
            } else {
                v[r][c] = make_float4(0.f, 0.f, 0.f, 0.f);
            }
        }
    }

    const float scale = 0.08838834764831845f; // 1/sqrt(128)
    const bool loHalf = lane < 16;

    // Per-lane partial scores for both pixels
    float sA[9], sB[9];
    {
        const float4 midA = v[1][1];
        const float4 midB = v[1][2];
#pragma unroll
        for (int n = 0; n < 9; ++n) {
            const float4 qa = v[n / 3][n % 3];
            const float4 qb = v[n / 3][n % 3 + 1];
            sA[n] = qa.x * midA.x + qa.y * midA.y + qa.z * midA.z + qa.w * midA.w;
            sB[n] = qb.x * midB.x + qb.y * midB.y + qb.z * midB.z + qb.w * midB.w;
        }
    }

    // Stage 16: fold both pixels, pack A into lanes 0-15, B into lanes 16-31
    float s[9];
#pragma unroll
    for (int n = 0; n < 9; ++n) {
        float tA = sA[n] + __shfl_xor_sync(0xffffffffu, sA[n], 16);
        float tB = sB[n] + __shfl_xor_sync(0xffffffffu, sB[n], 16);
        s[n] = loHalf ? tA : tB;
    }
    // Stages 8,4,2,1 within each 16-lane half
#pragma unroll
    for (int off = 8; off > 0; off >>= 1) {
#pragma unroll
        for (int n = 0; n < 9; ++n)
            s[n] += __shfl_xor_sync(0xffffffffu, s[n], off);
    }

    // Softmax for this lane's pixel only
    float mx = s[0];
#pragma unroll
    for (int n = 1; n < 9; ++n) mx = fmaxf(mx, s[n]);
    float a[9], den = 0.f;
#pragma unroll
    for (int n = 0; n < 9; ++n) {
        a[n] = __expf((s[n] - mx) * scale);
        den += a[n];
    }
    float inv = 1.0f / den;

    // Normalize and exchange weights across halves
    float wA[9], wB[9];
#pragma unroll
    for (int n = 0; n < 9; ++n) {
        float an = a[n] * inv;
        float other = __shfl_xor_sync(0xffffffffu, an, 16);
        wA[n] = loHalf ? an : other;
        wB[n] = loHalf ? other : an;
    }

    // Weighted sums (both pixels), write to smem stage
    float4 oA = make_float4(0.f, 0.f, 0.f, 0.f);
    float4 oB = make_float4(0.f, 0.f, 0.f, 0.f);
#pragma unroll
    for (int n = 0; n < 9; ++n) {
        const float4 qa = v[n / 3][n % 3];
        const float4 qb = v[n / 3][n % 3 + 1];
        oA.x = fmaf(wA[n], qa.x, oA.x);
        oA.y = fmaf(wA[n], qa.y, oA.y);
        oA.z = fmaf(wA[n], qa.z, oA.z);
        oA.w = fmaf(wA[n], qa.w, oA.w);
        oB.x = fmaf(wB[n], qb.x, oB.x);
        oB.y = fmaf(wB[n], qb.y, oB.y);
        oB.z = fmaf(wB[n], qb.z, oB.z);
        oB.w = fmaf(wB[n], qb.w, oB.w);
    }

    *reinterpret_cast<float4*>(&so[(wid * 2 + 0) * CO + lane * 4]) = oA;
    *reinterpret_cast<float4*>(&so[(wid * 2 + 1) * CO + lane * 4]) = oB;
    __syncthreads();

    // Transposed, channel-major store
    {
        const int c  = tid >> 1;
        const int qb = (tid & 1) * 2;
        float* dst = out + ((size_t)b * CO + c) * HW + h * WW + wc;
#pragma unroll
        for (int j = 0; j < 2; ++j) {
            int q = qb + j;
            float4 r;
            r.x = so[(q * 4 + 0) * CO + c];
            r.y = so[(q * 4 + 1) * CO + c];
            r.z = so[(q * 4 + 2) * CO + c];
            r.w = so[(q * 4 + 3) * CO + c];
            *reinterpret_cast<float4*>(dst + q * 4) = r;
        }
    }
}

// ---------------------------------------------------------------------------
extern "C" void kernel_launch(void* const* d_in, const int* in_sizes, int n_in,
                              void* d_out, int out_size)
{
    const float* x  = nullptr;
    const float* Wc = nullptr;
    const float* bc = nullptr;
    for (int i = 0; i < n_in; ++i) {
        if (in_sizes[i] == BATCH * CI * HW) x  = (const float*)d_in[i];
        else if (in_sizes[i] == CO * CI)    Wc = (const float*)d_in[i];
        else if (in_sizes[i] == CO)         bc = (const float*)d_in[i];
    }
    float* out = (float*)d_out;

    static const int conv_smem = 64 * 128 * 2 * sizeof(float);   // 65536

    cudaFuncSetAttribute(conv1x1_kernel,
                         cudaFuncAttributeMaxDynamicSharedMemorySize, conv_smem);

    conv1x1_kernel<<<dim3(HW / 128, BATCH), 256, conv_smem>>>(x, Wc, bc);
    attn3x3_kernel<<<BATCH * HW / 16, 256>>>(out);
}